// round 8
// baseline (speedup 1.0000x reference)
#include <cuda_runtime.h>
#include <cuda_bf16.h>

// Soft_NN forward == exact 1-NN: out[b,n,:] = y_c[b, argmin_m dist(x[b,n], y[b,m]), :]
//   dist = fl(fl(x2+y2) - 2*s), s = fp32 FMA dot product. fmaf(-2,s,x2+y2) is
//   bit-identical to fsub(fadd(x2,y2), fmul(2,s)) because 2*s is exact.
// R7: 512 threads/CTA (4 warps/SMSP), BM=256 — same FFMA2/LDS ratio, 2x warps
//     to hide LDS latency. Dynamic smem (~52KB).

#define B_  4
#define N_  4096
#define M_  4096
#define C_  32
#define BN  128
#define BM  256
#define NTHR 512
#define XSTR 132         // Xs row stride (floats), 16B-aligned rows
#define YSTR 260         // Ys row stride (floats), 16B-aligned rows

typedef unsigned long long u64v;

__device__ __forceinline__ u64v pack2(float lo, float hi) {
    u64v r;
    asm("mov.b64 %0, {%1, %2};" : "=l"(r)
        : "r"(__float_as_uint(lo)), "r"(__float_as_uint(hi)));
    return r;
}
__device__ __forceinline__ u64v fma2(u64v a, u64v b, u64v c) {
    u64v d;
    asm("fma.rn.f32x2 %0, %1, %2, %3;" : "=l"(d) : "l"(a), "l"(b), "l"(c));
    return d;
}
__device__ __forceinline__ void unpack2(u64v v, float& lo, float& hi) {
    unsigned ulo, uhi;
    asm("mov.b64 {%0, %1}, %2;" : "=r"(ulo), "=r"(uhi) : "l"(v));
    lo = __uint_as_float(ulo);
    hi = __uint_as_float(uhi);
}

// smem layout (floats): Xs[32][XSTR] | Ys[32][YSTR] | x2s[BN] | y2s[BM]
#define SMEM_FLOATS (C_ * XSTR + C_ * YSTR + BN + BM)

__global__ __launch_bounds__(NTHR, 1)
void soft_nn_kernel(const float* __restrict__ x,
                    const float* __restrict__ y,
                    const float* __restrict__ yc,
                    float* __restrict__ out)
{
    extern __shared__ __align__(16) float smem[];
    float (*Xs)[XSTR] = (float(*)[XSTR])smem;
    float (*Ys)[YSTR] = (float(*)[YSTR])(smem + C_ * XSTR);
    float* x2s = smem + C_ * XSTR + C_ * YSTR;
    float* y2s = x2s + BN;

    const int tid = threadIdx.x;
    const int tx  = tid & 31;        // 32 m-lanes (8 m each -> BM=256)
    const int ty  = tid >> 5;        // 16 n-lanes (8 n each -> BN=128); const per warp
    const int blk = blockIdx.x;      // 0..127
    const int b   = blk >> 5;        // 32 CTAs per batch
    const int n0  = (blk & 31) * BN;

    const float4* xg = (const float4*)(x + ((size_t)b * N_ + n0) * C_);
    const float4* yg = (const float4*)(y + (size_t)b * M_ * C_);

    // ---- load X tile [BN x C] transposed into Xs[C][BN] ----
    #pragma unroll
    for (int t = tid; t < BN * C_ / 4; t += NTHR) {
        int n  = t >> 3;             // 8 float4 per row (C=32)
        int c4 = (t & 7) << 2;
        float4 v = xg[t];
        Xs[c4 + 0][n] = v.x;
        Xs[c4 + 1][n] = v.y;
        Xs[c4 + 2][n] = v.z;
        Xs[c4 + 3][n] = v.w;
    }
    __syncthreads();
    if (tid < BN) {
        float s = 0.f;
        #pragma unroll
        for (int k = 0; k < C_; k++) { float v = Xs[k][tid]; s = fmaf(v, v, s); }
        x2s[tid] = s;
    }
    __syncthreads();                 // x2s visible to all

    float x2r[8];
    #pragma unroll
    for (int i = 0; i < 8; i++) x2r[i] = x2s[ty * 8 + i];

    // ---- prefetch first Y chunk into registers (BM*C/4 = 2048 = 512*4) ----
    float4 pf[4];
    #pragma unroll
    for (int r = 0; r < 4; r++) pf[r] = yg[tid + NTHR * r];

    float bestd[8];
    int   bestm[8];
    #pragma unroll
    for (int i = 0; i < 8; i++) { bestd[i] = 3.4e38f; bestm[i] = 0; }

    for (int mc = 0; mc < M_; mc += BM) {
        __syncthreads();  // previous chunk's compute done reading Ys/y2s

        // ---- store prefetched Y chunk transposed into Ys[C][BM] ----
        #pragma unroll
        for (int r = 0; r < 4; r++) {
            int t  = tid + NTHR * r;
            int m  = t >> 3;
            int c4 = (t & 7) << 2;
            float4 v = pf[r];
            Ys[c4 + 0][m] = v.x;
            Ys[c4 + 1][m] = v.y;
            Ys[c4 + 2][m] = v.z;
            Ys[c4 + 3][m] = v.w;
        }
        __syncthreads();
        if (tid < BM) {
            float s = 0.f;
            #pragma unroll
            for (int k = 0; k < C_; k++) { float v = Ys[k][tid]; s = fmaf(v, v, s); }
            y2s[tid] = s;
        }
        // issue next chunk's global loads (complete under the compute below)
        if (mc + BM < M_) {
            const float4* ygn = yg + ((mc + BM) * C_) / 4;
            #pragma unroll
            for (int r = 0; r < 4; r++) pf[r] = ygn[tid + NTHR * r];
        }
        __syncthreads();  // y2s ready

        // ---- packed 8x8 register tile via FFMA2: pairs along queries ----
        // thread's candidates: m = mc + tx*4 + j (j<4), mc + 128 + tx*4 + (j-4)
        u64v acc[4][8];
        #pragma unroll
        for (int i2 = 0; i2 < 4; i2++)
            #pragma unroll
            for (int j = 0; j < 8; j++) acc[i2][j] = 0ULL;

        #pragma unroll 8
        for (int k = 0; k < C_; k++) {
            ulonglong2 xp = *(const ulonglong2*)&Xs[k][ty * 8];       // broadcast in warp
            ulonglong2 xq = *(const ulonglong2*)&Xs[k][ty * 8 + 4];
            float4 ya = *(const float4*)&Ys[k][tx * 4];               // conflict-free
            float4 yb = *(const float4*)&Ys[k][128 + tx * 4];         // conflict-free
            u64v xpair[4] = { xp.x, xp.y, xq.x, xq.y };
            u64v yp[8] = {
                pack2(ya.x, ya.x), pack2(ya.y, ya.y), pack2(ya.z, ya.z), pack2(ya.w, ya.w),
                pack2(yb.x, yb.x), pack2(yb.y, yb.y), pack2(yb.z, yb.z), pack2(yb.w, yb.w)
            };
            #pragma unroll
            for (int i2 = 0; i2 < 4; i2++)
                #pragma unroll
                for (int j = 0; j < 8; j++)
                    acc[i2][j] = fma2(xpair[i2], yp[j], acc[i2][j]);
        }

        // ---- argmin update (reference rounding; 2*s exact => fmaf identical) ----
        float yyr[8];
        int   mr[8];
        #pragma unroll
        for (int j = 0; j < 8; j++) {
            int mloc = (j < 4) ? (tx * 4 + j) : (128 + tx * 4 + (j - 4));
            yyr[j] = y2s[mloc];
            mr[j]  = mc + mloc;
        }
        #pragma unroll
        for (int i2 = 0; i2 < 4; i2++) {
            #pragma unroll
            for (int j = 0; j < 8; j++) {
                float slo, shi;
                unpack2(acc[i2][j], slo, shi);
                float dlo = fmaf(-2.0f, slo, __fadd_rn(x2r[2 * i2],     yyr[j]));
                float dhi = fmaf(-2.0f, shi, __fadd_rn(x2r[2 * i2 + 1], yyr[j]));
                // strict < keeps earliest m per thread (j and mc both ascend in m)
                if (dlo < bestd[2 * i2])     { bestd[2 * i2]     = dlo; bestm[2 * i2]     = mr[j]; }
                if (dhi < bestd[2 * i2 + 1]) { bestd[2 * i2 + 1] = dhi; bestm[2 * i2 + 1] = mr[j]; }
            }
        }
    }

    // ---- cross-tx reduction (reuse smem tiles as scratch) ----
    __syncthreads();
    float* redD = &Ys[0][0];         // BN*32 = 4096 floats (fits 32*260)
    int*   redM = (int*)&Xs[0][0];   // 4096 ints (fits 32*132)
    #pragma unroll
    for (int i = 0; i < 8; i++) {
        int n = ty * 8 + i;
        redD[n * 32 + tx] = bestd[i];
        redM[n * 32 + tx] = bestm[i];
    }
    __syncthreads();
    if (tid < BN) {
        float bd = redD[tid * 32];
        int   bm = redM[tid * 32];
        #pragma unroll
        for (int t = 1; t < 32; t++) {
            float d = redD[tid * 32 + t];
            int   m = redM[tid * 32 + t];
            if (d < bd || (d == bd && m < bm)) { bd = d; bm = m; }
        }
        const float* src = yc + ((size_t)b * M_ + bm) * 3;
        float*       dst = out + ((size_t)b * N_ + n0 + tid) * 3;
        dst[0] = src[0];
        dst[1] = src[1];
        dst[2] = src[2];
    }
}

extern "C" void kernel_launch(void* const* d_in, const int* in_sizes, int n_in,
                              void* d_out, int out_size)
{
    const float* x  = (const float*)d_in[0];   // x_f  [4,4096,32]
    const float* y  = (const float*)d_in[1];   // y_f  [4,4096,32]
    const float* yc = (const float*)d_in[2];   // y_c  [4,4096,3]
    // d_in[3] = temp_inv (positive constant; does not affect argmax)
    float* out = (float*)d_out;                // [4,4096,3]

    const int smem_bytes = SMEM_FLOATS * (int)sizeof(float);  // ~52KB
    cudaFuncSetAttribute(soft_nn_kernel,
                         cudaFuncAttributeMaxDynamicSharedMemorySize, smem_bytes);
    soft_nn_kernel<<<(B_ * N_) / BN, NTHR, smem_bytes>>>(x, y, yc, out);
}